// round 14
// baseline (speedup 1.0000x reference)
#include <cuda_runtime.h>
#include <math.h>

#define N_NAMED 8000
#define N_TOTAL 8192
#define DIM 128
#define BLOCKS 128
#define THREADS 256
#define WARPS 8
#define RPB (N_TOTAL / BLOCKS)   // 64 rows per block
#define RPW (RPB / WARPS)        // 8 rows per warp

// Cross-block scratch (no cudaMalloc allowed).
__device__ float              g_pmax[BLOCKS];       // per-block dr-max (release-ordered)
__device__ unsigned           g_bar  = 0;           // monotone ticket — NEVER reset
__device__ unsigned long long g_done = 0;           // (epoch << 32) | bits(global max)

__device__ __forceinline__ unsigned arrive_acq_rel(unsigned* p) {
    unsigned old;
    asm volatile("atom.acq_rel.gpu.global.add.u32 %0, [%1], 1;"
                 : "=r"(old) : "l"(p) : "memory");
    return old;
}
__device__ __forceinline__ float ld_acq_f(const float* p) {
    float v;
    asm volatile("ld.acquire.gpu.global.f32 %0, [%1];" : "=f"(v) : "l"(p) : "memory");
    return v;
}
__device__ __forceinline__ void st_rel_f(float* p, float v) {
    asm volatile("st.release.gpu.global.f32 [%0], %1;" :: "l"(p), "f"(v) : "memory");
}
__device__ __forceinline__ void st_rel64(unsigned long long* p, unsigned long long v) {
    asm volatile("st.release.gpu.global.u64 [%0], %1;" :: "l"(p), "l"(v) : "memory");
}
__device__ __forceinline__ unsigned long long ld_rlx64(const unsigned long long* p) {
    unsigned long long v;
    asm volatile("ld.relaxed.gpu.global.u64 %0, [%1];" : "=l"(v) : "l"(p) : "memory");
    return v;
}

__global__ void __launch_bounds__(THREADS)
falcon_fused(const float* __restrict__ anon,
             const float* __restrict__ etab,
             const float* __restrict__ ctab,
             const float* __restrict__ rtab,
             const float* __restrict__ w,    // [256]: w_l | w_r
             const float* __restrict__ bptr,
             const int*   __restrict__ cid,
             const int*   __restrict__ rid,
             float*       __restrict__ out)
{
    __shared__ float s_w[2 * DIM];
    __shared__ float s_dl[RPB];
    __shared__ float s_max[WARPS];
    __shared__ float s_scal[3];        // c_dot, r_dot, b
    __shared__ float s_cmax;

    const int tid  = threadIdx.x;
    const int warp = tid >> 5;
    const int lane = tid & 31;
    const int bid  = blockIdx.x;

    // ---- prologue EXACTLY as R4/R13 (empirically fastest; do not reorder) ----
    s_w[tid] = w[tid];
    __syncthreads();

    const float4 wl = reinterpret_cast<const float4*>(s_w)[lane];
    const float4 wr = reinterpret_cast<const float4*>(s_w + DIM)[lane];

    const int base = bid * RPB + warp * RPW;
    float4 v[RPW];
#pragma unroll
    for (int k = 0; k < RPW; ++k) {
        const int r = base + k;
        const float* e = (r < N_NAMED)
                           ? (etab + (size_t)r * DIM)
                           : (anon + (size_t)(r - N_NAMED) * DIM);
        v[k] = reinterpret_cast<const float4*>(e)[lane];
    }

    // ---- Phase A: w_r dots -> block max -> publish ASAP ----
    float lmax = -3.4e38f;
#pragma unroll
    for (int k = 0; k < RPW; ++k) {
        float dr = v[k].x * wr.x + v[k].y * wr.y + v[k].z * wr.z + v[k].w * wr.w;
#pragma unroll
        for (int o = 16; o > 0; o >>= 1)
            dr += __shfl_xor_sync(0xffffffffu, dr, o);
        lmax = fmaxf(lmax, dr);
    }
    if (lane == 0) s_max[warp] = lmax;
    __syncthreads();

    unsigned epoch = 0;
    bool     is_last = false;
    if (tid == 0) {
        float m = s_max[0];
#pragma unroll
        for (int i = 1; i < WARPS; ++i) m = fmaxf(m, s_max[i]);
        st_rel_f(&g_pmax[bid], m);                 // value (release-ordered by add below)
        const unsigned t = arrive_acq_rel(&g_bar); // ticket
        epoch   = t / BLOCKS + 1u;                 // same for all blocks this replay
        is_last = (t == epoch * BLOCKS - 1u);
    }

    // ---- Phase B (overlaps other blocks' publishes): w_l dots ----
#pragma unroll
    for (int k = 0; k < RPW; ++k) {
        float dl = v[k].x * wl.x + v[k].y * wl.y + v[k].z * wl.z + v[k].w * wl.w;
#pragma unroll
        for (int o = 16; o > 0; o >>= 1)
            dl += __shfl_xor_sync(0xffffffffu, dl, o);
        if (lane == 0) s_dl[warp * RPW + k] = dl;
    }

    // ---- Phase C (also overlapped): scalar dots in warp 1 ----
    if (warp == 1) {
        const float* ce = ctab + (size_t)__ldg(cid) * DIM;
        const float* re = rtab + (size_t)__ldg(rid) * DIM;
        const float4 cv = __ldg(reinterpret_cast<const float4*>(ce) + lane);
        const float4 rv = __ldg(reinterpret_cast<const float4*>(re) + lane);
        float cd = cv.x * wl.x + cv.y * wl.y + cv.z * wl.z + cv.w * wl.w;
        float rd = rv.x * wl.x + rv.y * wl.y + rv.z * wl.z + rv.w * wl.w;
#pragma unroll
        for (int o = 16; o > 0; o >>= 1) {
            cd += __shfl_xor_sync(0xffffffffu, cd, o);
            rd += __shfl_xor_sync(0xffffffffu, rd, o);
        }
        if (lane == 0) {
            s_scal[0] = cd;
            s_scal[1] = rd;
            s_scal[2] = __ldg(bptr);
        }
    }
    __syncthreads();   // s_dl / s_scal ready for everyone (off critical path)

    // ---- hoist exponentials OFF the tail:
    //      sigma(x + cmax) = 1 / (1 + e^-x * e^-cmax)
    float E = 0.f, Ec = 0.f;
    if (tid < RPB) {
        const float b = s_scal[2];
        E  = __expf(-(s_dl[tid] + s_scal[1] + b));
        Ec = __expf(-(s_scal[0] + b));
    }

    // ---- rendezvous: last arriver gathers+broadcasts; others poll ONE 8B word ----
    if (tid == 0) {
        float m;
        if (is_last) {
            m = -3.4e38f;
#pragma unroll 4
            for (int i = 0; i < BLOCKS; ++i)
                m = fmaxf(m, ld_acq_f(&g_pmax[i]));    // 4 L2 lines, pipelined
            st_rel64(&g_done,
                     ((unsigned long long)epoch << 32) |
                     (unsigned long long)__float_as_uint(m));
        } else {
            unsigned long long p = ld_rlx64(&g_done);
            while ((unsigned)(p >> 32) != epoch)       // value rides with the tag
                p = ld_rlx64(&g_done);
            m = __uint_as_float((unsigned)p);
        }
        s_cmax = m;
    }
    __syncthreads();

    // ---- outputs: exact collapse (both sigmoid factors strictly increase in
    //      col_j, so argmax_j sits at col_max for every i) ----
    if (tid < RPB) {
        const float K   = __expf(-s_cmax);
        const float rfs = 1.f / (1.f + E  * K);
        const float cfs = 1.f / (1.f + Ec * K);
        out[bid * RPB + tid] = rfs * cfs;
    }
}

extern "C" void kernel_launch(void* const* d_in, const int* in_sizes, int n_in,
                              void* d_out, int out_size) {
    const float* anon = (const float*)d_in[0];   // [192,128]
    const float* etab = (const float*)d_in[1];   // [8000,128]
    const float* ctab = (const float*)d_in[2];   // [100,128]
    const float* rtab = (const float*)d_in[3];   // [50,128]
    const float* w    = (const float*)d_in[4];   // [1,256]
    const float* bb   = (const float*)d_in[5];   // [1]
    const int*   cid  = (const int*)d_in[6];
    const int*   rid  = (const int*)d_in[7];

    falcon_fused<<<BLOCKS, THREADS>>>(anon, etab, ctab, rtab, w, bb, cid, rid,
                                      (float*)d_out);
}

// round 15
// speedup vs baseline: 3.8229x; 3.8229x over previous
#include <cuda_runtime.h>
#include <math.h>

#define N_NAMED 8000
#define N_TOTAL 8192
#define DIM 128
#define BLOCKS 128
#define THREADS 256
#define WARPS 8
#define RPB (N_TOTAL / BLOCKS)   // 64 rows per block
#define RPW (RPB / WARPS)        // 8 rows per warp

// Cross-block scratch (no cudaMalloc allowed).
__device__ float              g_pmax[BLOCKS];   // per-block dr-max
__device__ unsigned           g_bar  = 0;       // monotone ticket — NEVER reset
__device__ unsigned long long g_done = 0;       // (epoch << 32) | bits(global max)

__device__ __forceinline__ unsigned arrive_acq_rel(unsigned* p) {
    unsigned old;
    asm volatile("atom.acq_rel.gpu.global.add.u32 %0, [%1], 1;"
                 : "=r"(old) : "l"(p) : "memory");
    return old;
}
__device__ __forceinline__ float ld_rlx_f(const float* p) {
    float v;
    asm volatile("ld.relaxed.gpu.global.f32 %0, [%1];" : "=f"(v) : "l"(p) : "memory");
    return v;
}
__device__ __forceinline__ void st_rel_f(float* p, float v) {
    asm volatile("st.release.gpu.global.f32 [%0], %1;" :: "l"(p), "f"(v) : "memory");
}
__device__ __forceinline__ void st_rel64(unsigned long long* p, unsigned long long v) {
    asm volatile("st.release.gpu.global.u64 [%0], %1;" :: "l"(p), "l"(v) : "memory");
}
__device__ __forceinline__ unsigned long long ld_rlx64(const unsigned long long* p) {
    unsigned long long v;
    asm volatile("ld.relaxed.gpu.global.u64 %0, [%1];" : "=l"(v) : "l"(p) : "memory");
    return v;
}

__global__ void __launch_bounds__(THREADS)
falcon_fused(const float* __restrict__ anon,
             const float* __restrict__ etab,
             const float* __restrict__ ctab,
             const float* __restrict__ rtab,
             const float* __restrict__ w,    // [256]: w_l | w_r
             const float* __restrict__ bptr,
             const int*   __restrict__ cid,
             const int*   __restrict__ rid,
             float*       __restrict__ out)
{
    __shared__ float    s_w[2 * DIM];
    __shared__ float    s_dl[RPB];
    __shared__ float    s_max[WARPS];
    __shared__ float    s_scal[3];     // c_dot, r_dot, b
    __shared__ float    s_cmax;
    __shared__ unsigned s_ticket;

    const int tid  = threadIdx.x;
    const int warp = tid >> 5;
    const int lane = tid & 31;
    const int bid  = blockIdx.x;

    // ---- prologue EXACTLY as R4/R13 (empirically fastest; do not reorder) ----
    s_w[tid] = w[tid];
    __syncthreads();

    const float4 wl = reinterpret_cast<const float4*>(s_w)[lane];
    const float4 wr = reinterpret_cast<const float4*>(s_w + DIM)[lane];

    const int base = bid * RPB + warp * RPW;
    float4 v[RPW];
#pragma unroll
    for (int k = 0; k < RPW; ++k) {
        const int r = base + k;
        const float* e = (r < N_NAMED)
                           ? (etab + (size_t)r * DIM)
                           : (anon + (size_t)(r - N_NAMED) * DIM);
        v[k] = reinterpret_cast<const float4*>(e)[lane];
    }

    // ---- Phase A: w_r dots -> block max -> publish ASAP ----
    float lmax = -3.4e38f;
#pragma unroll
    for (int k = 0; k < RPW; ++k) {
        float dr = v[k].x * wr.x + v[k].y * wr.y + v[k].z * wr.z + v[k].w * wr.w;
#pragma unroll
        for (int o = 16; o > 0; o >>= 1)
            dr += __shfl_xor_sync(0xffffffffu, dr, o);
        lmax = fmaxf(lmax, dr);
    }
    if (lane == 0) s_max[warp] = lmax;
    __syncthreads();

    if (tid == 0) {
        float m = s_max[0];
#pragma unroll
        for (int i = 1; i < WARPS; ++i) m = fmaxf(m, s_max[i]);
        st_rel_f(&g_pmax[bid], m);                 // value, ordered by release-add below
        s_ticket = arrive_acq_rel(&g_bar);         // ticket (acq_rel)
    }

    // ---- Phase B (overlaps other blocks' publishes): w_l dots ----
#pragma unroll
    for (int k = 0; k < RPW; ++k) {
        float dl = v[k].x * wl.x + v[k].y * wl.y + v[k].z * wl.z + v[k].w * wl.w;
#pragma unroll
        for (int o = 16; o > 0; o >>= 1)
            dl += __shfl_xor_sync(0xffffffffu, dl, o);
        if (lane == 0) s_dl[warp * RPW + k] = dl;
    }

    // ---- Phase C (also overlapped): scalar dots in warp 1 ----
    if (warp == 1) {
        const float* ce = ctab + (size_t)__ldg(cid) * DIM;
        const float* re = rtab + (size_t)__ldg(rid) * DIM;
        const float4 cv = __ldg(reinterpret_cast<const float4*>(ce) + lane);
        const float4 rv = __ldg(reinterpret_cast<const float4*>(re) + lane);
        float cd = cv.x * wl.x + cv.y * wl.y + cv.z * wl.z + cv.w * wl.w;
        float rd = rv.x * wl.x + rv.y * wl.y + rv.z * wl.z + rv.w * wl.w;
#pragma unroll
        for (int o = 16; o > 0; o >>= 1) {
            cd += __shfl_xor_sync(0xffffffffu, cd, o);
            rd += __shfl_xor_sync(0xffffffffu, rd, o);
        }
        if (lane == 0) {
            s_scal[0] = cd;
            s_scal[1] = rd;
            s_scal[2] = __ldg(bptr);
        }
    }
    __syncthreads();   // publishes s_ticket/s_dl/s_scal; extends tid0's acquire block-wide

    // ---- hoist exponentials OFF the tail: sigma(x+cmax)=1/(1+e^-x * e^-cmax) ----
    float E = 0.f, Ec = 0.f;
    if (tid < RPB) {
        const float b = s_scal[2];
        E  = __expf(-(s_dl[tid] + s_scal[1] + b));
        Ec = __expf(-(s_scal[0] + b));
    }

    // ---- rendezvous: last arriver gathers (warp-parallel, RELAXED) + broadcasts;
    //      others poll ONE 8B word (tag and value arrive together) ----
    if (warp == 0) {
        const unsigned t     = s_ticket;
        const unsigned epoch = t / BLOCKS + 1u;
        if (t == epoch * BLOCKS - 1u) {
            // happens-before: our acq_rel ticket saw all release-adds, each of
            // which was release-ordered after its block's g_pmax store.
            // Relaxed loads pipeline freely (the R14 bug was serial acquires).
            float m = fmaxf(fmaxf(ld_rlx_f(&g_pmax[lane]),
                                  ld_rlx_f(&g_pmax[lane + 32])),
                            fmaxf(ld_rlx_f(&g_pmax[lane + 64]),
                                  ld_rlx_f(&g_pmax[lane + 96])));
#pragma unroll
            for (int o = 16; o > 0; o >>= 1)
                m = fmaxf(m, __shfl_xor_sync(0xffffffffu, m, o));
            if (lane == 0) {
                st_rel64(&g_done,
                         ((unsigned long long)epoch << 32) |
                         (unsigned long long)__float_as_uint(m));
                s_cmax = m;
            }
        } else if (lane == 0) {
            unsigned long long p = ld_rlx64(&g_done);
            while ((unsigned)(p >> 32) != epoch)
                p = ld_rlx64(&g_done);
            s_cmax = __uint_as_float((unsigned)p);
        }
    }
    __syncthreads();

    // ---- outputs: exact collapse (both sigmoid factors strictly increase in
    //      col_j, so argmax_j sits at col_max for every i) ----
    if (tid < RPB) {
        const float K   = __expf(-s_cmax);
        const float rfs = 1.f / (1.f + E  * K);
        const float cfs = 1.f / (1.f + Ec * K);
        out[bid * RPB + tid] = rfs * cfs;
    }
}

extern "C" void kernel_launch(void* const* d_in, const int* in_sizes, int n_in,
                              void* d_out, int out_size) {
    const float* anon = (const float*)d_in[0];   // [192,128]
    const float* etab = (const float*)d_in[1];   // [8000,128]
    const float* ctab = (const float*)d_in[2];   // [100,128]
    const float* rtab = (const float*)d_in[3];   // [50,128]
    const float* w    = (const float*)d_in[4];   // [1,256]
    const float* bb   = (const float*)d_in[5];   // [1]
    const int*   cid  = (const int*)d_in[6];
    const int*   rid  = (const int*)d_in[7];

    falcon_fused<<<BLOCKS, THREADS>>>(anon, etab, ctab, rtab, w, bb, cid, rid,
                                      (float*)d_out);
}